// round 1
// baseline (speedup 1.0000x reference)
#include <cuda_runtime.h>
#include <cuda_bf16.h>
#include <cstdint>

#define N_NODES 100000
#define N_EDGES 1600000
#define F_IN    128
#define F_HID   64
#define F_OUT   40

// ---------------- scratch (static device globals; no allocation) ----------------
__device__ float g_degs[N_NODES];          // out-degree (over src)
__device__ float g_degd[N_NODES];          // in-degree  (over dst)
__device__ float g_ns[N_NODES];            // rsqrt(max(out_deg,1))
__device__ float g_nd[N_NODES];            // rsqrt(max(in_deg,1))
__device__ float g_bufA[(size_t)N_NODES * F_HID];  // xw (GEMM output)
__device__ float g_bufB[(size_t)N_NODES * F_HID];  // aggregation target
__device__ float g_bufC[(size_t)N_NODES * F_OUT];  // layer-2 xw

// ---------------- utility kernels ----------------
__global__ void k_zero2(float* __restrict__ a, int n, float* __restrict__ b, int m) {
    int i = blockIdx.x * blockDim.x + threadIdx.x;
    if (i < n) a[i] = 0.0f;
    if (i < m) b[i] = 0.0f;
}

__global__ void k_zero4(float4* __restrict__ p, int n4) {
    int i = blockIdx.x * blockDim.x + threadIdx.x;
    if (i < n4) p[i] = make_float4(0.f, 0.f, 0.f, 0.f);
}

__global__ void k_deg(const int* __restrict__ src, const int* __restrict__ dst) {
    int e = blockIdx.x * blockDim.x + threadIdx.x;
    if (e < N_EDGES) {
        atomicAdd(&g_degs[src[e]], 1.0f);
        atomicAdd(&g_degd[dst[e]], 1.0f);
    }
}

__global__ void k_norm() {
    int i = blockIdx.x * blockDim.x + threadIdx.x;
    if (i < N_NODES) {
        g_ns[i] = rsqrtf(fmaxf(g_degs[i], 1.0f));
        g_nd[i] = rsqrtf(fmaxf(g_degd[i], 1.0f));
    }
}

// ---------------- tiled fp32 GEMM: Y[N,M] = op(X)[N,K] @ W[K,M], row-scaled ----------------
// op(X) (PRE=true):  x = relu(x * g_nd[row] + bpre[k])   (fuses previous layer's epilogue)
// output:            y = acc * g_ns[row]
// Tile: 64 rows x 64 cols per block, 256 threads, 4x4 microtile, K-chunks of 16.
template <int K, int M, bool PRE>
__global__ __launch_bounds__(256) void k_gemm(const float* __restrict__ X,
                                              const float* __restrict__ W,
                                              float* __restrict__ Y,
                                              const float* __restrict__ bpre) {
    __shared__ __align__(16) float Xs[16][72];  // transposed: Xs[k][row]; stride 72 kills STS conflicts
    __shared__ __align__(16) float Ws[16][64];

    const int tid  = threadIdx.x;
    const int tx   = tid & 15;   // col group (4 cols each)
    const int ty   = tid >> 4;   // row group (4 rows each)
    const int row0 = blockIdx.x * 64;

    const int lr = tid >> 2;     // load-phase row 0..63
    const int lq = tid & 3;      // load-phase k-quad 0..3
    const int lrow = row0 + lr;

    float ndv = 1.0f;
    if (PRE) ndv = (lrow < N_NODES) ? g_nd[lrow] : 0.0f;

    float acc[4][4];
#pragma unroll
    for (int i = 0; i < 4; i++)
#pragma unroll
        for (int j = 0; j < 4; j++) acc[i][j] = 0.0f;

    for (int kc = 0; kc < K; kc += 16) {
        // --- load X tile (64 rows x 16 k), transposed into Xs ---
        float4 xv = make_float4(0.f, 0.f, 0.f, 0.f);
        if (lrow < N_NODES)
            xv = *(const float4*)&X[(size_t)lrow * K + kc + lq * 4];
        if (PRE) {
            xv.x = fmaxf(fmaf(xv.x, ndv, __ldg(&bpre[kc + lq * 4 + 0])), 0.f);
            xv.y = fmaxf(fmaf(xv.y, ndv, __ldg(&bpre[kc + lq * 4 + 1])), 0.f);
            xv.z = fmaxf(fmaf(xv.z, ndv, __ldg(&bpre[kc + lq * 4 + 2])), 0.f);
            xv.w = fmaxf(fmaf(xv.w, ndv, __ldg(&bpre[kc + lq * 4 + 3])), 0.f);
        }
        Xs[lq * 4 + 0][lr] = xv.x;
        Xs[lq * 4 + 1][lr] = xv.y;
        Xs[lq * 4 + 2][lr] = xv.z;
        Xs[lq * 4 + 3][lr] = xv.w;

        // --- load W tile (16 k x 64 cols), zero-padded past M ---
        {
            const int wk = ty;       // 0..15
            const int wc = tx * 4;   // 0..60
            float4 wv = make_float4(0.f, 0.f, 0.f, 0.f);
            if (wc < M)
                wv = *(const float4*)&W[(size_t)(kc + wk) * M + wc];
            *(float4*)&Ws[wk][wc] = wv;
        }
        __syncthreads();

#pragma unroll
        for (int k = 0; k < 16; k++) {
            float4 a = *(const float4*)&Xs[k][ty * 4];
            float4 b = *(const float4*)&Ws[k][tx * 4];
            acc[0][0] += a.x * b.x; acc[0][1] += a.x * b.y; acc[0][2] += a.x * b.z; acc[0][3] += a.x * b.w;
            acc[1][0] += a.y * b.x; acc[1][1] += a.y * b.y; acc[1][2] += a.y * b.z; acc[1][3] += a.y * b.w;
            acc[2][0] += a.z * b.x; acc[2][1] += a.z * b.y; acc[2][2] += a.z * b.z; acc[2][3] += a.z * b.w;
            acc[3][0] += a.w * b.x; acc[3][1] += a.w * b.y; acc[3][2] += a.w * b.z; acc[3][3] += a.w * b.w;
        }
        __syncthreads();
    }

    // --- epilogue: scale by norm_src and store ---
    const int c = tx * 4;
#pragma unroll
    for (int i = 0; i < 4; i++) {
        const int rr = row0 + ty * 4 + i;
        if (rr < N_NODES && c < M) {
            const float s = g_ns[rr];
            float4 o;
            o.x = acc[i][0] * s;
            o.y = acc[i][1] * s;
            o.z = acc[i][2] * s;
            o.w = acc[i][3] * s;
            *(float4*)&Y[(size_t)rr * M + c] = o;
        }
    }
}

// ---------------- edge scatter: agg[dst] += xw[src], 64-wide rows ----------------
// 16 threads per edge, float4 per thread, vector reduction (no return value).
__global__ __launch_bounds__(256) void k_scatter64(const float* __restrict__ xw,
                                                   float* __restrict__ agg,
                                                   const int* __restrict__ src,
                                                   const int* __restrict__ dst) {
    long long idx = (long long)blockIdx.x * blockDim.x + threadIdx.x;
    if (idx >= (long long)N_EDGES * 16) return;
    const int e = (int)(idx >> 4);
    const int f = ((int)idx & 15) << 2;
    const int s = __ldg(&src[e]);
    const int d = __ldg(&dst[e]);
    const float4 v = __ldg((const float4*)&xw[(size_t)s * 64 + f]);
    asm volatile("red.global.add.v4.f32 [%0], {%1,%2,%3,%4};"
                 :: "l"(&agg[(size_t)d * 64 + f]),
                    "f"(v.x), "f"(v.y), "f"(v.z), "f"(v.w)
                 : "memory");
}

// 40-wide rows: 10 float4 per edge.
__global__ __launch_bounds__(256) void k_scatter40(const float* __restrict__ xw,
                                                   float* __restrict__ agg,
                                                   const int* __restrict__ src,
                                                   const int* __restrict__ dst) {
    long long idx = (long long)blockIdx.x * blockDim.x + threadIdx.x;
    if (idx >= (long long)N_EDGES * 10) return;
    const int e = (int)(idx / 10);
    const int f = ((int)(idx - (long long)e * 10)) << 2;
    const int s = __ldg(&src[e]);
    const int d = __ldg(&dst[e]);
    const float4 v = __ldg((const float4*)&xw[(size_t)s * 40 + f]);
    asm volatile("red.global.add.v4.f32 [%0], {%1,%2,%3,%4};"
                 :: "l"(&agg[(size_t)d * 40 + f]),
                    "f"(v.x), "f"(v.y), "f"(v.z), "f"(v.w)
                 : "memory");
}

// ---------------- final epilogue: out = out * norm_dst[row] + b2[col] ----------------
__global__ void k_epilogue(float* __restrict__ out, const float* __restrict__ b2) {
    int i = blockIdx.x * blockDim.x + threadIdx.x;
    if (i < N_NODES * F_OUT) {
        const int r = i / F_OUT;
        const int c = i - r * F_OUT;
        out[i] = fmaf(out[i], g_nd[r], __ldg(&b2[c]));
    }
}

// ---------------- host launch ----------------
extern "C" void kernel_launch(void* const* d_in, const int* in_sizes, int n_in,
                              void* d_out, int out_size) {
    (void)in_sizes; (void)n_in; (void)out_size;
    const float* h  = (const float*)d_in[0];
    const float* W0 = (const float*)d_in[1];
    const float* b0 = (const float*)d_in[2];
    const float* W1 = (const float*)d_in[3];
    const float* b1 = (const float*)d_in[4];
    const float* W2 = (const float*)d_in[5];
    const float* b2 = (const float*)d_in[6];
    const int*   src = (const int*)d_in[7];
    const int*   dst = (const int*)d_in[8];
    float* out = (float*)d_out;

    float *pA, *pB, *pC, *pdegs, *pdegd;
    cudaGetSymbolAddress((void**)&pA, g_bufA);
    cudaGetSymbolAddress((void**)&pB, g_bufB);
    cudaGetSymbolAddress((void**)&pC, g_bufC);
    cudaGetSymbolAddress((void**)&pdegs, g_degs);
    cudaGetSymbolAddress((void**)&pdegd, g_degd);

    const int nodeBlocks  = (N_NODES + 255) / 256;
    const int edgeBlocks  = (N_EDGES + 255) / 256;
    const int gemmBlocks  = (N_NODES + 63) / 64;
    const int hid4        = N_NODES * F_HID / 4;   // float4 count

    // degrees + norms
    k_zero2<<<nodeBlocks, 256>>>(pdegs, N_NODES, pdegd, N_NODES);
    k_deg<<<edgeBlocks, 256>>>(src, dst);
    k_norm<<<nodeBlocks, 256>>>();

    // layer 0: bufA = (h @ W0) * ns ; bufB = 0 ; bufB += scatter(bufA)
    k_gemm<F_IN, F_HID, false><<<gemmBlocks, 256>>>(h, W0, pA, b0);
    k_zero4<<<(hid4 + 255) / 256, 256>>>((float4*)pB, hid4);
    k_scatter64<<<(int)(((long long)N_EDGES * 16 + 255) / 256), 256>>>(pA, pB, src, dst);

    // layer 1: bufA = (relu(bufB*nd + b0) @ W1) * ns ; bufB = 0 ; bufB += scatter(bufA)
    k_gemm<F_HID, F_HID, true><<<gemmBlocks, 256>>>(pB, W1, pA, b0);
    k_zero4<<<(hid4 + 255) / 256, 256>>>((float4*)pB, hid4);
    k_scatter64<<<(int)(((long long)N_EDGES * 16 + 255) / 256), 256>>>(pA, pB, src, dst);

    // layer 2: bufC = (relu(bufB*nd + b1) @ W2) * ns ; out = 0 ; out += scatter(bufC)
    k_gemm<F_HID, F_OUT, true><<<gemmBlocks, 256>>>(pB, W2, pC, b1);
    {
        const int out4 = N_NODES * F_OUT / 4;
        k_zero4<<<(out4 + 255) / 256, 256>>>((float4*)out, out4);
    }
    k_scatter40<<<(int)(((long long)N_EDGES * 10 + 255) / 256), 256>>>(pC, out, src, dst);

    // out = out * nd + b2
    k_epilogue<<<(N_NODES * F_OUT + 255) / 256, 256>>>(out, b2);
}

// round 2
// speedup vs baseline: 1.5348x; 1.5348x over previous
#include <cuda_runtime.h>
#include <cuda_bf16.h>
#include <cstdint>

#define N_NODES 100000
#define N_EDGES 1600000
#define F_IN    128
#define F_HID   64
#define F_OUT   40

#define SCAN_T  1024
#define SCAN_NB ((N_NODES + SCAN_T - 1) / SCAN_T)   // 98

// ---------------- scratch (static device globals; no allocation) ----------------
__device__ int   g_degs_i[N_NODES];            // out-degree (src histogram)
__device__ int   g_degd_i[N_NODES];            // in-degree  (dst histogram)
__device__ float g_ns[N_NODES];                // rsqrt(max(out_deg,1))
__device__ float g_nd[N_NODES];                // rsqrt(max(in_deg,1))
__device__ int   g_incl[N_NODES];              // per-chunk inclusive scan
__device__ int   g_rowoff[N_NODES + 1];        // CSR row offsets (by dst)
__device__ int   g_cursor[N_NODES];            // fill cursors
__device__ int   g_partial[SCAN_NB];
__device__ int   g_poff[SCAN_NB];
__device__ int   g_csrc[N_EDGES];              // src id per dst-grouped edge
__device__ float g_bufA[(size_t)N_NODES * F_HID];
__device__ float g_bufB[(size_t)N_NODES * F_HID];
__device__ float g_bufC[(size_t)N_NODES * F_OUT];

// ---------------- degree histograms + norms ----------------
__global__ void k_zero_deg() {
    int i = blockIdx.x * blockDim.x + threadIdx.x;
    if (i < N_NODES) { g_degs_i[i] = 0; g_degd_i[i] = 0; }
}

__global__ void k_deg(const int* __restrict__ src, const int* __restrict__ dst) {
    int e = blockIdx.x * blockDim.x + threadIdx.x;
    if (e < N_EDGES) {
        atomicAdd(&g_degs_i[src[e]], 1);
        atomicAdd(&g_degd_i[dst[e]], 1);
    }
}

__global__ void k_norm() {
    int i = blockIdx.x * blockDim.x + threadIdx.x;
    if (i < N_NODES) {
        g_ns[i] = rsqrtf(fmaxf((float)g_degs_i[i], 1.0f));
        g_nd[i] = rsqrtf(fmaxf((float)g_degd_i[i], 1.0f));
    }
}

// ---------------- CSR build: scan of in-degrees ----------------
__global__ __launch_bounds__(SCAN_T) void k_scan_block() {
    __shared__ int ws[32];
    int g = blockIdx.x * SCAN_T + threadIdx.x;
    int lane = threadIdx.x & 31, wid = threadIdx.x >> 5;
    int x = (g < N_NODES) ? g_degd_i[g] : 0;
#pragma unroll
    for (int o = 1; o < 32; o <<= 1) {
        int y = __shfl_up_sync(0xFFFFFFFFu, x, o);
        if (lane >= o) x += y;
    }
    if (lane == 31) ws[wid] = x;
    __syncthreads();
    if (wid == 0) {
        int y = ws[lane];
#pragma unroll
        for (int o = 1; o < 32; o <<= 1) {
            int z = __shfl_up_sync(0xFFFFFFFFu, y, o);
            if (lane >= o) y += z;
        }
        ws[lane] = y;
    }
    __syncthreads();
    int incl = x + (wid > 0 ? ws[wid - 1] : 0);
    if (g < N_NODES) g_incl[g] = incl;
    if (threadIdx.x == SCAN_T - 1) g_partial[blockIdx.x] = incl;
}

__global__ void k_scan_partials() {
    if (threadIdx.x == 0 && blockIdx.x == 0) {
        int run = 0;
        for (int i = 0; i < SCAN_NB; i++) { g_poff[i] = run; run += g_partial[i]; }
    }
}

__global__ __launch_bounds__(SCAN_T) void k_finalize() {
    int g = blockIdx.x * SCAN_T + threadIdx.x;
    if (g < N_NODES) {
        int incl = g_incl[g] + g_poff[blockIdx.x];
        g_rowoff[g + 1] = incl;
        g_cursor[g] = incl - g_degd_i[g];   // exclusive offset
        if (g == 0) g_rowoff[0] = 0;
    }
}

__global__ void k_fill(const int* __restrict__ src, const int* __restrict__ dst) {
    int e = blockIdx.x * blockDim.x + threadIdx.x;
    if (e < N_EDGES) {
        int d = dst[e];
        int slot = atomicAdd(&g_cursor[d], 1);
        g_csrc[slot] = src[e];
    }
}

// ---------------- tiled fp32 GEMM: Y[N,M] = op(X)[N,K] @ W[K,M], row-scaled ----------------
// 128 rows x 64 cols per block, 256 threads, 8x4 microtile, K-chunks of 16.
// op(X) (PRE): x' = relu(x * g_nd[row] + bpre[k]); output: y = acc * g_ns[row].
template <int K, int M, bool PRE>
__global__ __launch_bounds__(256) void k_gemm(const float* __restrict__ X,
                                              const float* __restrict__ W,
                                              float* __restrict__ Y,
                                              const float* __restrict__ bpre) {
    __shared__ __align__(16) float Xs[16][132];  // transposed: Xs[k][row], pad 4
    __shared__ __align__(16) float Ws[16][64];

    const int tid  = threadIdx.x;
    const int tx   = tid & 15;    // col group (4 cols)
    const int ty   = tid >> 4;    // row group (8 rows)
    const int row0 = blockIdx.x * 128;

    const int lr   = tid >> 1;    // X-load row 0..127
    const int lq   = tid & 1;     // X-load base quad
    const int lrow = row0 + lr;

    float ndv = 1.0f;
    if (PRE) ndv = (lrow < N_NODES) ? g_nd[lrow] : 0.0f;

    float acc[8][4];
#pragma unroll
    for (int i = 0; i < 8; i++)
#pragma unroll
        for (int j = 0; j < 4; j++) acc[i][j] = 0.0f;

    for (int kc = 0; kc < K; kc += 16) {
        // X tile: 128 rows x 16 k, transposed; each thread loads 2 float4
#pragma unroll
        for (int q = 0; q < 2; q++) {
            const int kq = lq + q * 2;            // 0..3
            float4 xv = make_float4(0.f, 0.f, 0.f, 0.f);
            if (lrow < N_NODES)
                xv = *(const float4*)&X[(size_t)lrow * K + kc + kq * 4];
            if (PRE) {
                xv.x = fmaxf(fmaf(xv.x, ndv, __ldg(&bpre[kc + kq * 4 + 0])), 0.f);
                xv.y = fmaxf(fmaf(xv.y, ndv, __ldg(&bpre[kc + kq * 4 + 1])), 0.f);
                xv.z = fmaxf(fmaf(xv.z, ndv, __ldg(&bpre[kc + kq * 4 + 2])), 0.f);
                xv.w = fmaxf(fmaf(xv.w, ndv, __ldg(&bpre[kc + kq * 4 + 3])), 0.f);
            }
            Xs[kq * 4 + 0][lr] = xv.x;
            Xs[kq * 4 + 1][lr] = xv.y;
            Xs[kq * 4 + 2][lr] = xv.z;
            Xs[kq * 4 + 3][lr] = xv.w;
        }
        // W tile: 16 k x 64 cols; one float4 per thread
        {
            const int wk = tid >> 4;
            const int wc = (tid & 15) * 4;
            float4 wv = make_float4(0.f, 0.f, 0.f, 0.f);
            if (wc < M)
                wv = *(const float4*)&W[(size_t)(kc + wk) * M + wc];
            *(float4*)&Ws[wk][wc] = wv;
        }
        __syncthreads();

#pragma unroll
        for (int k = 0; k < 16; k++) {
            const float4 b  = *(const float4*)&Ws[k][tx * 4];
            const float4 a0 = *(const float4*)&Xs[k][ty * 8];
            const float4 a1 = *(const float4*)&Xs[k][ty * 8 + 4];
            acc[0][0] += a0.x * b.x; acc[0][1] += a0.x * b.y; acc[0][2] += a0.x * b.z; acc[0][3] += a0.x * b.w;
            acc[1][0] += a0.y * b.x; acc[1][1] += a0.y * b.y; acc[1][2] += a0.y * b.z; acc[1][3] += a0.y * b.w;
            acc[2][0] += a0.z * b.x; acc[2][1] += a0.z * b.y; acc[2][2] += a0.z * b.z; acc[2][3] += a0.z * b.w;
            acc[3][0] += a0.w * b.x; acc[3][1] += a0.w * b.y; acc[3][2] += a0.w * b.z; acc[3][3] += a0.w * b.w;
            acc[4][0] += a1.x * b.x; acc[4][1] += a1.x * b.y; acc[4][2] += a1.x * b.z; acc[4][3] += a1.x * b.w;
            acc[5][0] += a1.y * b.x; acc[5][1] += a1.y * b.y; acc[5][2] += a1.y * b.z; acc[5][3] += a1.y * b.w;
            acc[6][0] += a1.z * b.x; acc[6][1] += a1.z * b.y; acc[6][2] += a1.z * b.z; acc[6][3] += a1.z * b.w;
            acc[7][0] += a1.w * b.x; acc[7][1] += a1.w * b.y; acc[7][2] += a1.w * b.z; acc[7][3] += a1.w * b.w;
        }
        __syncthreads();
    }

    const int c = tx * 4;
#pragma unroll
    for (int i = 0; i < 8; i++) {
        const int rr = row0 + ty * 8 + i;
        if (rr < N_NODES && c < M) {
            const float s = g_ns[rr];
            float4 o;
            o.x = acc[i][0] * s; o.y = acc[i][1] * s;
            o.z = acc[i][2] * s; o.w = acc[i][3] * s;
            *(float4*)&Y[(size_t)rr * M + c] = o;
        }
    }
}

// ---------------- CSR gather aggregation (no atomics) ----------------
// 16 threads per node, float4 per thread; 4-way unrolled for MLP.
__global__ __launch_bounds__(256) void k_gather64(const float* __restrict__ xw,
                                                  float* __restrict__ agg) {
    const int node = blockIdx.x * 16 + (threadIdx.x >> 4);
    if (node >= N_NODES) return;
    const int f   = (threadIdx.x & 15) << 2;
    int       i   = g_rowoff[node];
    const int end = g_rowoff[node + 1];
    float4 acc = make_float4(0.f, 0.f, 0.f, 0.f);
    for (; i + 3 < end; i += 4) {
        const int s0 = __ldg(&g_csrc[i + 0]);
        const int s1 = __ldg(&g_csrc[i + 1]);
        const int s2 = __ldg(&g_csrc[i + 2]);
        const int s3 = __ldg(&g_csrc[i + 3]);
        const float4 v0 = __ldg((const float4*)&xw[(size_t)s0 * 64 + f]);
        const float4 v1 = __ldg((const float4*)&xw[(size_t)s1 * 64 + f]);
        const float4 v2 = __ldg((const float4*)&xw[(size_t)s2 * 64 + f]);
        const float4 v3 = __ldg((const float4*)&xw[(size_t)s3 * 64 + f]);
        acc.x += v0.x + v1.x + v2.x + v3.x;
        acc.y += v0.y + v1.y + v2.y + v3.y;
        acc.z += v0.z + v1.z + v2.z + v3.z;
        acc.w += v0.w + v1.w + v2.w + v3.w;
    }
    for (; i < end; i++) {
        const int s = __ldg(&g_csrc[i]);
        const float4 v = __ldg((const float4*)&xw[(size_t)s * 64 + f]);
        acc.x += v.x; acc.y += v.y; acc.z += v.z; acc.w += v.w;
    }
    *(float4*)&agg[(size_t)node * 64 + f] = acc;
}

// 40-wide gather with fused final epilogue: out = sum * nd[node] + b2[col]
__global__ __launch_bounds__(256) void k_gather40(const float* __restrict__ xw,
                                                  float* __restrict__ out,
                                                  const float* __restrict__ b2) {
    const int node = blockIdx.x * 16 + (threadIdx.x >> 4);
    if (node >= N_NODES) return;
    const int f = (threadIdx.x & 15) << 2;
    if (f >= F_OUT) return;
    int       i   = g_rowoff[node];
    const int end = g_rowoff[node + 1];
    float4 acc = make_float4(0.f, 0.f, 0.f, 0.f);
    for (; i + 3 < end; i += 4) {
        const int s0 = __ldg(&g_csrc[i + 0]);
        const int s1 = __ldg(&g_csrc[i + 1]);
        const int s2 = __ldg(&g_csrc[i + 2]);
        const int s3 = __ldg(&g_csrc[i + 3]);
        const float4 v0 = __ldg((const float4*)&xw[(size_t)s0 * F_OUT + f]);
        const float4 v1 = __ldg((const float4*)&xw[(size_t)s1 * F_OUT + f]);
        const float4 v2 = __ldg((const float4*)&xw[(size_t)s2 * F_OUT + f]);
        const float4 v3 = __ldg((const float4*)&xw[(size_t)s3 * F_OUT + f]);
        acc.x += v0.x + v1.x + v2.x + v3.x;
        acc.y += v0.y + v1.y + v2.y + v3.y;
        acc.z += v0.z + v1.z + v2.z + v3.z;
        acc.w += v0.w + v1.w + v2.w + v3.w;
    }
    for (; i < end; i++) {
        const int s = __ldg(&g_csrc[i]);
        const float4 v = __ldg((const float4*)&xw[(size_t)s * F_OUT + f]);
        acc.x += v.x; acc.y += v.y; acc.z += v.z; acc.w += v.w;
    }
    const float nd = g_nd[node];
    float4 o;
    o.x = fmaf(acc.x, nd, __ldg(&b2[f + 0]));
    o.y = fmaf(acc.y, nd, __ldg(&b2[f + 1]));
    o.z = fmaf(acc.z, nd, __ldg(&b2[f + 2]));
    o.w = fmaf(acc.w, nd, __ldg(&b2[f + 3]));
    *(float4*)&out[(size_t)node * F_OUT + f] = o;
}

// ---------------- host launch ----------------
extern "C" void kernel_launch(void* const* d_in, const int* in_sizes, int n_in,
                              void* d_out, int out_size) {
    (void)in_sizes; (void)n_in; (void)out_size;
    const float* h   = (const float*)d_in[0];
    const float* W0  = (const float*)d_in[1];
    const float* b0  = (const float*)d_in[2];
    const float* W1  = (const float*)d_in[3];
    const float* b1  = (const float*)d_in[4];
    const float* W2  = (const float*)d_in[5];
    const float* b2  = (const float*)d_in[6];
    const int*   src = (const int*)d_in[7];
    const int*   dst = (const int*)d_in[8];
    float* out = (float*)d_out;

    float *pA, *pB, *pC;
    cudaGetSymbolAddress((void**)&pA, g_bufA);
    cudaGetSymbolAddress((void**)&pB, g_bufB);
    cudaGetSymbolAddress((void**)&pC, g_bufC);

    const int nodeBlocks = (N_NODES + 255) / 256;
    const int edgeBlocks = (N_EDGES + 255) / 256;
    const int gemmBlocks = (N_NODES + 127) / 128;
    const int gathBlocks = (N_NODES + 15) / 16;

    // degrees, norms, CSR
    k_zero_deg<<<nodeBlocks, 256>>>();
    k_deg<<<edgeBlocks, 256>>>(src, dst);
    k_norm<<<nodeBlocks, 256>>>();
    k_scan_block<<<SCAN_NB, SCAN_T>>>();
    k_scan_partials<<<1, 32>>>();
    k_finalize<<<SCAN_NB, SCAN_T>>>();
    k_fill<<<edgeBlocks, 256>>>(src, dst);

    // layer 0
    k_gemm<F_IN, F_HID, false><<<gemmBlocks, 256>>>(h, W0, pA, b0);
    k_gather64<<<gathBlocks, 256>>>(pA, pB);
    // layer 1
    k_gemm<F_HID, F_HID, true><<<gemmBlocks, 256>>>(pB, W1, pA, b0);
    k_gather64<<<gathBlocks, 256>>>(pA, pB);
    // layer 2 (+ fused bias/norm epilogue in gather)
    k_gemm<F_HID, F_OUT, true><<<gemmBlocks, 256>>>(pB, W2, pC, b1);
    k_gather40<<<gathBlocks, 256>>>(pC, out, b2);
}